// round 2
// baseline (speedup 1.0000x reference)
#include <cuda_runtime.h>
#include <cstdint>

#define N_NODES 100000
#define N_EDGES 1600000
#define CH      128
#define EDIM    16

// ---------------- scratch (static device globals: no allocation) ----------------
__device__ float g_nodeproj[(size_t)N_NODES * CH];
__device__ float g_summed [(size_t)N_NODES * CH];
__device__ float g_h      [(size_t)N_NODES * CH];
__device__ float g_inv    [N_NODES];
__device__ int   g_cnt    [N_NODES];
__device__ int   g_is64;

// ---------------- packed f32x2 helpers (sm_103a) ----------------
static __device__ __forceinline__ unsigned long long pack2(float x, float y) {
    unsigned long long r;
    asm("mov.b64 %0, {%1, %2};" : "=l"(r) : "f"(x), "f"(y));
    return r;
}
static __device__ __forceinline__ void unpack2(unsigned long long v, float &x, float &y) {
    asm("mov.b64 {%0, %1}, %2;" : "=f"(x), "=f"(y) : "l"(v));
}
static __device__ __forceinline__ void ffma2(unsigned long long &d,
                                             unsigned long long a,
                                             unsigned long long b) {
    asm("fma.rn.f32x2 %0, %1, %2, %0;" : "+l"(d) : "l"(a), "l"(b));
}

// ---------------- dtype sniffer for edge_index (int32 vs int64) ----------------
// Node ids < 100000 < 2^31, so if the buffer is int64, every odd 32-bit word is 0.
// If int32, odd words are random node ids (P(zero)≈1e-5 each).
__global__ void detect_kernel(const unsigned* __restrict__ p) {
    __shared__ int nz;
    if (threadIdx.x == 0) nz = 0;
    __syncthreads();
    unsigned v = p[threadIdx.x * 2 + 1];
    if (v != 0u) atomicAdd(&nz, 1);
    __syncthreads();
    if (threadIdx.x == 0) g_is64 = (nz == 0) ? 1 : 0;
}

static __device__ __forceinline__ int load_eidx(const void* eidx, long long i, int is64) {
    return is64 ? (int)((const long long*)eidx)[i] : ((const int*)eidx)[i];
}

// ---------------- zero / count / inv ----------------
__global__ void zero_summed_kernel() {
    size_t i = (size_t)blockIdx.x * blockDim.x + threadIdx.x;
    if (i < (size_t)N_NODES * (CH / 4))
        reinterpret_cast<float4*>(g_summed)[i] = make_float4(0.f, 0.f, 0.f, 0.f);
}
__global__ void zero_cnt_kernel() {
    int i = blockIdx.x * blockDim.x + threadIdx.x;
    if (i < N_NODES) g_cnt[i] = 0;
}
__global__ void count_kernel(const void* __restrict__ eidx) {
    long long t = (long long)blockIdx.x * blockDim.x + threadIdx.x;
    if (t >= N_EDGES) return;
    int dst = load_eidx(eidx, (long long)N_EDGES + t, g_is64);
    atomicAdd(&g_cnt[dst], 1);
}
__global__ void inv_kernel() {
    int n = blockIdx.x * blockDim.x + threadIdx.x;
    if (n < N_NODES) {
        int c = g_cnt[n];
        g_inv[n] = 1.0f / (float)(c > 1 ? c : 1);
    }
}

// ---------------- tiled GEMM: C[N,128] = A[N,KTOT] @ B[KTOT,128] (+epilogue) ----
// A is [A0 | A1*inv[row]] when AGG (KTOT=256). BM=BN=128, BK=16, 256 thr, 8x8/thr.
// NORM: add bias1, L2-normalize rows, add bias2 (opt RELU). else: add bias1 only.
template<int KTOT, bool AGG, bool NORM, bool RELU>
__global__ __launch_bounds__(256)
void gemm_kernel(const float* __restrict__ A0, const float* __restrict__ A1,
                 const float* __restrict__ inv,
                 const float* __restrict__ B,
                 const float* __restrict__ bias1, const float* __restrict__ bias2,
                 float* __restrict__ out)
{
    __shared__ float As[16 * 128];
    __shared__ float Bs[16 * 128];
    const int tid = threadIdx.x;
    const int tx = tid & 15, ty = tid >> 4;
    const int row0 = blockIdx.x * 128;

    unsigned long long acc[8][4];
#pragma unroll
    for (int i = 0; i < 8; i++)
#pragma unroll
        for (int j = 0; j < 4; j++) acc[i][j] = 0ull;

    for (int kb = 0; kb < KTOT; kb += 16) {
        // A tile -> As[k][m] (transposed)
#pragma unroll
        for (int it = 0; it < 2; it++) {
            int f = tid + it * 256;        // 0..511 float4 chunks
            int m = f >> 2;                // 0..127
            int k4 = (f & 3) << 2;         // 0,4,8,12
            int grow = row0 + m;
            float4 v = make_float4(0.f, 0.f, 0.f, 0.f);
            if (grow < N_NODES) {
                if (!AGG || kb < 128) {
                    v = *reinterpret_cast<const float4*>(&A0[(size_t)grow * 128 + kb + k4]);
                } else {
                    v = *reinterpret_cast<const float4*>(&A1[(size_t)grow * 128 + (kb - 128) + k4]);
                    float s = inv[grow];
                    v.x *= s; v.y *= s; v.z *= s; v.w *= s;
                }
            }
            As[(k4 + 0) * 128 + m] = v.x;
            As[(k4 + 1) * 128 + m] = v.y;
            As[(k4 + 2) * 128 + m] = v.z;
            As[(k4 + 3) * 128 + m] = v.w;
        }
        // B tile -> Bs[k][n]
#pragma unroll
        for (int it = 0; it < 2; it++) {
            int f = tid + it * 256;
            int k = f >> 5;
            int n4 = f & 31;
            reinterpret_cast<float4*>(Bs)[f] =
                reinterpret_cast<const float4*>(&B[(size_t)(kb + k) * 128])[n4];
        }
        __syncthreads();
#pragma unroll
        for (int k = 0; k < 16; k++) {
            float4 a0 = *reinterpret_cast<const float4*>(&As[k * 128 + ty * 8]);
            float4 a1 = *reinterpret_cast<const float4*>(&As[k * 128 + ty * 8 + 4]);
            ulonglong2 bb0 = *reinterpret_cast<const ulonglong2*>(&Bs[k * 128 + tx * 8]);
            ulonglong2 bb1 = *reinterpret_cast<const ulonglong2*>(&Bs[k * 128 + tx * 8 + 4]);
            float av[8] = {a0.x, a0.y, a0.z, a0.w, a1.x, a1.y, a1.z, a1.w};
            unsigned long long bv[4] = {bb0.x, bb0.y, bb1.x, bb1.y};
#pragma unroll
            for (int i = 0; i < 8; i++) {
                unsigned long long a2 = pack2(av[i], av[i]);
#pragma unroll
                for (int j = 0; j < 4; j++) ffma2(acc[i][j], a2, bv[j]);
            }
        }
        __syncthreads();
    }

    // epilogue
    float vals[8][8];
#pragma unroll
    for (int i = 0; i < 8; i++)
#pragma unroll
        for (int j = 0; j < 4; j++)
            unpack2(acc[i][j], vals[i][2 * j], vals[i][2 * j + 1]);

#pragma unroll
    for (int j = 0; j < 8; j++) {
        float b = bias1[tx * 8 + j];
#pragma unroll
        for (int i = 0; i < 8; i++) vals[i][j] += b;
    }

    float rn[8];
    if (NORM) {
        float* ss = As;  // reuse (safe: loop ended with __syncthreads)
        if (tid < 128) ss[tid] = 0.f;
        __syncthreads();
#pragma unroll
        for (int i = 0; i < 8; i++) {
            float p = 0.f;
#pragma unroll
            for (int j = 0; j < 8; j++) p += vals[i][j] * vals[i][j];
            atomicAdd(&ss[ty * 8 + i], p);
        }
        __syncthreads();
        if (tid < 128) {
            float s = ss[tid];
            Bs[tid] = 1.0f / fmaxf(sqrtf(s), 1e-12f);
        }
        __syncthreads();
#pragma unroll
        for (int i = 0; i < 8; i++) rn[i] = Bs[ty * 8 + i];
    }

#pragma unroll
    for (int i = 0; i < 8; i++) {
        int grow = row0 + ty * 8 + i;
        if (grow < N_NODES) {
            float o[8];
#pragma unroll
            for (int j = 0; j < 8; j++) {
                float v = vals[i][j];
                if (NORM) v = v * rn[i] + bias2[tx * 8 + j];
                if (RELU) v = fmaxf(v, 0.f);
                o[j] = v;
            }
            float4* dst = reinterpret_cast<float4*>(&out[(size_t)grow * 128 + tx * 8]);
            dst[0] = make_float4(o[0], o[1], o[2], o[3]);
            dst[1] = make_float4(o[4], o[5], o[6], o[7]);
        }
    }
}

// ---------------- fused edge kernel --------------------------------------------
// warp per edge: msg = relu(nodeproj[src] + ea @ We); summed[dst] += msg (red.v4)
__global__ __launch_bounds__(256)
void edge_kernel(const float* __restrict__ nodeproj,
                 const float* __restrict__ edge_attr,
                 const void* __restrict__ eidx,
                 const float* __restrict__ We,   // [16][128] row-major
                 float* __restrict__ summed)
{
    __shared__ ulonglong2 sWe[16 * 32];  // 8 KB: per (k, lane) a float4 of W_e
    for (int i = threadIdx.x; i < 512; i += 256)
        sWe[i] = reinterpret_cast<const ulonglong2*>(We)[i];
    __syncthreads();

    const int lane = threadIdx.x & 31;
    const int warp = threadIdx.x >> 5;
    const int is64 = g_is64;
    const long long nwarps = (long long)gridDim.x * (blockDim.x >> 5);
    const long long* e64 = (const long long*)eidx;
    const int* e32 = (const int*)eidx;

    for (long long e = (long long)blockIdx.x * 8 + warp; e < N_EDGES; e += nwarps) {
        int src, dst;
        if (is64) { src = (int)e64[e]; dst = (int)e64[N_EDGES + e]; }
        else      { src = e32[e];      dst = e32[N_EDGES + e]; }

        float eav = 0.f;
        if (lane < 16) eav = edge_attr[e * 16 + lane];

        float4 np4 = reinterpret_cast<const float4*>(nodeproj)[(size_t)src * 32 + lane];
        unsigned long long acc0 = pack2(np4.x, np4.y);
        unsigned long long acc1 = pack2(np4.z, np4.w);

#pragma unroll
        for (int k = 0; k < 16; k++) {
            float a = __shfl_sync(0xffffffffu, eav, k);
            unsigned long long a2 = pack2(a, a);
            ulonglong2 w = sWe[k * 32 + lane];
            ffma2(acc0, a2, w.x);
            ffma2(acc1, a2, w.y);
        }
        float r0, r1, r2, r3;
        unpack2(acc0, r0, r1);
        unpack2(acc1, r2, r3);
        r0 = fmaxf(r0, 0.f); r1 = fmaxf(r1, 0.f);
        r2 = fmaxf(r2, 0.f); r3 = fmaxf(r3, 0.f);

        float* p = &summed[(size_t)dst * 128 + lane * 4];
        asm volatile("red.global.add.v4.f32 [%0], {%1,%2,%3,%4};"
                     :: "l"(p), "f"(r0), "f"(r1), "f"(r2), "f"(r3) : "memory");
    }
}

// ---------------- launch -------------------------------------------------------
extern "C" void kernel_launch(void* const* d_in, const int* in_sizes, int n_in,
                              void* d_out, int out_size)
{
    const float* x         = (const float*)d_in[0];
    const void*  edge_idx  = d_in[1];
    const float* edge_attr = (const float*)d_in[2];
    const float* w_msg1    = (const float*)d_in[3];
    const float* b_msg1    = (const float*)d_in[4];
    const float* w_upd1    = (const float*)d_in[5];
    const float* b_upd1    = (const float*)d_in[6];
    const float* bias1     = (const float*)d_in[7];
    const float* w_msg2    = (const float*)d_in[8];
    const float* b_msg2    = (const float*)d_in[9];
    const float* w_upd2    = (const float*)d_in[10];
    const float* b_upd2    = (const float*)d_in[11];
    const float* bias2     = (const float*)d_in[12];
    float* out = (float*)d_out;

    float *np, *sm, *h, *inv;
    cudaGetSymbolAddress((void**)&np,  g_nodeproj);
    cudaGetSymbolAddress((void**)&sm,  g_summed);
    cudaGetSymbolAddress((void**)&h,   g_h);
    cudaGetSymbolAddress((void**)&inv, g_inv);

    const int GEMM_BLOCKS = (N_NODES + 127) / 128;          // 782
    const int ZS_BLOCKS   = (N_NODES * (CH / 4) + 255) / 256;
    const int CNT_BLOCKS  = (N_EDGES + 255) / 256;
    const int NODE_BLOCKS = (N_NODES + 255) / 256;
    const int EDGE_BLOCKS = 4096;

    // dtype sniff + degree counts (shared by both layers)
    detect_kernel<<<1, 256>>>((const unsigned*)edge_idx);
    zero_cnt_kernel<<<NODE_BLOCKS, 256>>>();
    count_kernel<<<CNT_BLOCKS, 256>>>(edge_idx);
    inv_kernel<<<NODE_BLOCKS, 256>>>();

    // ---- layer 1 ----
    gemm_kernel<128, false, false, false><<<GEMM_BLOCKS, 256>>>(
        x, nullptr, nullptr, w_msg1, b_msg1, nullptr, np);
    zero_summed_kernel<<<ZS_BLOCKS, 256>>>();
    edge_kernel<<<EDGE_BLOCKS, 256>>>(np, edge_attr, edge_idx,
                                      w_msg1 + 128 * 128, sm);
    gemm_kernel<256, true, true, true><<<GEMM_BLOCKS, 256>>>(
        x, sm, inv, w_upd1, b_upd1, bias1, h);   // h = relu(layer1 out)

    // ---- layer 2 ----
    gemm_kernel<128, false, false, false><<<GEMM_BLOCKS, 256>>>(
        h, nullptr, nullptr, w_msg2, b_msg2, nullptr, np);
    zero_summed_kernel<<<ZS_BLOCKS, 256>>>();
    edge_kernel<<<EDGE_BLOCKS, 256>>>(np, edge_attr, edge_idx,
                                      w_msg2 + 128 * 128, sm);
    gemm_kernel<256, true, true, false><<<GEMM_BLOCKS, 256>>>(
        h, sm, inv, w_upd2, b_upd2, bias2, out);

    (void)in_sizes; (void)n_in; (void)out_size;
}